// round 1
// baseline (speedup 1.0000x reference)
#include <cuda_runtime.h>

#define NB 8
#define NC 96
#define NH 128
#define NW 128
#define EPSV 1e-5f
#define NTAP 10

// scratch (device globals: no allocation allowed)
__device__ float g_out[(size_t)NB * NC * NH * NW];
__device__ float g_rowmean[NB * NC * NH];
__device__ float g_colmean[NB * NC * NW];
__device__ float g_ah[NB * NC * NH];
__device__ float g_aw[NB * NC * NW];

// dynamic smem layout (floats):
//   [0, 12288)            s_sm   (m+l pre-GEMM activations, 96x128)
//   [12288, 24576)        a_sm   (anchor, 96x128)
//   [24576, 24576+2688)   phase-A weights, reused as w_fuse chunk in phase B
//   [27264, 27264+288)    fSc/fBi/aA (fused-BN scale/bias, prelu slope)
#define SM_FLOATS (2 * NC * NW + 2688 + 3 * NC)

__global__ void __launch_bounds__(256, 2)
k_main(const float* __restrict__ x,
       const float* __restrict__ r_m,  const float* __restrict__ wh_m,
       const float* __restrict__ ww_m, const float* __restrict__ r_l,
       const float* __restrict__ wh_l, const float* __restrict__ ww_l,
       const float* __restrict__ w_fuse,
       const float* __restrict__ bnf_g, const float* __restrict__ bnf_b,
       const float* __restrict__ bnf_m, const float* __restrict__ bnf_v,
       const float* __restrict__ dg_wh, const float* __restrict__ dg_ww,
       const float* __restrict__ dg_g,  const float* __restrict__ dg_b,
       const float* __restrict__ dg_m,  const float* __restrict__ dg_v,
       const float* __restrict__ act_a)
{
    extern __shared__ float sm[];
    float* s_sm = sm;
    float* a_sm = sm + NC * NW;
    float* wreg = sm + 2 * NC * NW;        // 2688 floats, reused in phase B
    float* wH   = wreg;                    // NC*10
    float* wW   = wreg + NC * NTAP;        // NC*10
    float* dgh  = wreg + 2 * NC * NTAP;    // NC*3
    float* dgw  = dgh + NC * 3;            // NC*3
    float* aSc  = dgw + NC * 3;            // NC
    float* aBi  = aSc + NC;                // NC
    float* fSc  = sm + 2 * NC * NW + 2688;
    float* fBi  = fSc + NC;
    float* aA   = fBi + NC;

    __shared__ int   s_off[NTAP];
    __shared__ float s_frac[NTAP];

    const int tid = threadIdx.x;
    const int b = blockIdx.y;
    const int h = blockIdx.x;

    // ---- stage weights / fold BN params ----
    if (tid < NTAP) {
        float r = fmaxf((tid < 5 ? r_m[0] : r_l[0]), 1.0f);
        int jo = (tid < 5) ? (tid - 2) : (tid - 7);
        float sh = (float)jo * r;
        float f = floorf(sh);
        s_off[tid]  = (int)f;
        s_frac[tid] = sh - f;
    }
    for (int i = tid; i < NC * 5; i += 256) {
        int c = i / 5, j = i % 5;
        wH[c * NTAP + j]     = wh_m[i];
        wH[c * NTAP + 5 + j] = wh_l[i];
        wW[c * NTAP + j]     = ww_m[i];
        wW[c * NTAP + 5 + j] = ww_l[i];
    }
    for (int i = tid; i < NC * 3; i += 256) { dgh[i] = dg_wh[i]; dgw[i] = dg_ww[i]; }
    for (int i = tid; i < NC; i += 256) {
        float sA = dg_g[i] * rsqrtf(dg_v[i] + EPSV);
        aSc[i] = sA;
        aBi[i] = dg_b[i] - sA * dg_m[i];
        float sF = bnf_g[i] * rsqrtf(bnf_v[i] + EPSV);
        fSc[i] = sF;
        fBi[i] = bnf_b[i] - sF * bnf_m[i];
        aA[i]  = act_a[i];
    }
    __syncthreads();

    // ---- phase A: build s = m + l and anchor for all 96 channels of this (b,h) row ----
    for (int idx = tid; idx < NC * NW; idx += 256) {
        int ci = idx >> 7;
        int w  = idx & (NW - 1);
        const float* bp = x + ((size_t)(b * NC + ci)) * (NH * NW);
        float xc = bp[h * NW + w];
        float sv = 2.0f * xc;
        #pragma unroll
        for (int j = 0; j < NTAP; j++) {
            int o = s_off[j];
            float fr = s_frac[j];
            int hh = h + o, wp = w + o;
            float vh = ((unsigned)hh < NH) ? bp[hh * NW + w] : 0.0f;
            float vw = ((unsigned)wp < NW) ? bp[h * NW + wp] : 0.0f;
            if (fr != 0.0f) {   // uniform branch; false for integer shifts
                float vh2 = ((unsigned)(hh + 1) < NH) ? bp[(hh + 1) * NW + w] : 0.0f;
                float vw2 = ((unsigned)(wp + 1) < NW) ? bp[h * NW + wp + 1] : 0.0f;
                vh = (1.0f - fr) * vh + fr * vh2;
                vw = (1.0f - fr) * vw + fr * vw2;
            }
            sv += wH[ci * NTAP + j] * vh + wW[ci * NTAP + j] * vw;
        }
        s_sm[idx] = sv;

        // anchor = BN(x + dwconv3_H + dwconv3_W)
        float up = (h > 0)      ? bp[(h - 1) * NW + w] : 0.0f;
        float dn = (h < NH - 1) ? bp[(h + 1) * NW + w] : 0.0f;
        float lf = (w > 0)      ? bp[h * NW + w - 1]   : 0.0f;
        float rt = (w < NW - 1) ? bp[h * NW + w + 1]   : 0.0f;
        float e = dgh[ci * 3 + 0] * up + dgh[ci * 3 + 1] * xc + dgh[ci * 3 + 2] * dn
                + dgw[ci * 3 + 0] * lf + dgw[ci * 3 + 1] * xc + dgw[ci * 3 + 2] * rt;
        a_sm[idx] = aSc[ci] * (xc + e) + aBi[ci];
    }
    __syncthreads();

    // ---- phase B: 96(out) x 128(pix) x 96(k) GEMM from smem ----
    const int lane = tid & 31;
    const int oT = tid >> 5;       // 8 o-tiles of 12
    const int ob = oT * 12;
    const int p = lane * 4;        // 32 p-tiles of 4

    float4 acc[12];
    #pragma unroll
    for (int i = 0; i < 12; i++) acc[i] = make_float4(0.f, 0.f, 0.f, 0.f);

    for (int c0 = 0; c0 < NC; c0 += 24) {
        __syncthreads();  // everyone done with previous wreg contents
        for (int i = tid; i < 24 * NC; i += 256) {
            int o = i / 24, cl = i % 24;
            wreg[cl * NC + o] = w_fuse[o * NC + (c0 + cl)];   // transpose into [cl][o]
        }
        __syncthreads();
        #pragma unroll
        for (int cl = 0; cl < 24; cl++) {
            int ci = c0 + cl;
            float4 sv = *(const float4*)(s_sm + ci * NW + p);
            const float4* wp4 = (const float4*)(wreg + cl * NC + ob);
            float4 w0 = wp4[0], w1 = wp4[1], w2 = wp4[2];
            float wv[12] = {w0.x, w0.y, w0.z, w0.w, w1.x, w1.y, w1.z, w1.w,
                            w2.x, w2.y, w2.z, w2.w};
            #pragma unroll
            for (int oo = 0; oo < 12; oo++) {
                acc[oo].x = fmaf(wv[oo], sv.x, acc[oo].x);
                acc[oo].y = fmaf(wv[oo], sv.y, acc[oo].y);
                acc[oo].z = fmaf(wv[oo], sv.z, acc[oo].z);
                acc[oo].w = fmaf(wv[oo], sv.w, acc[oo].w);
            }
        }
    }

    // ---- epilogue: BN-fold, +anchor, PReLU, write out + row means ----
    #pragma unroll
    for (int oo = 0; oo < 12; oo++) {
        int o = ob + oo;
        float sc = fSc[o], bi = fBi[o], al = aA[o];
        float4 an = *(const float4*)(a_sm + o * NW + p);
        float4 v;
        v.x = fmaf(acc[oo].x, sc, bi) + an.x;
        v.y = fmaf(acc[oo].y, sc, bi) + an.y;
        v.z = fmaf(acc[oo].z, sc, bi) + an.z;
        v.w = fmaf(acc[oo].w, sc, bi) + an.w;
        v.x = (v.x >= 0.f) ? v.x : al * v.x;
        v.y = (v.y >= 0.f) ? v.y : al * v.y;
        v.z = (v.z >= 0.f) ? v.z : al * v.z;
        v.w = (v.w >= 0.f) ? v.w : al * v.w;
        *(float4*)(g_out + ((size_t)(b * NC + o) * NH + h) * NW + p) = v;

        float ps = v.x + v.y + v.z + v.w;
        #pragma unroll
        for (int s2 = 16; s2 > 0; s2 >>= 1)
            ps += __shfl_xor_sync(0xffffffffu, ps, s2);
        if (lane == 0)
            g_rowmean[(b * NC + o) * NH + h] = ps * (1.0f / NW);
    }
}

__global__ void k_colmean()
{
    int i = blockIdx.x * blockDim.x + threadIdx.x;   // B*C*W
    if (i >= NB * NC * NW) return;
    int w = i & (NW - 1);
    int bc = i >> 7;
    const float* p = g_out + (size_t)bc * NH * NW + w;
    float s = 0.f;
    #pragma unroll 8
    for (int h = 0; h < NH; h++) s += p[h * NW];
    g_colmean[i] = s * (1.0f / NH);
}

__global__ void k_attn(const float* __restrict__ ca_w1,
                       const float* __restrict__ ca_g, const float* __restrict__ ca_b,
                       const float* __restrict__ ca_m, const float* __restrict__ ca_v,
                       const float* __restrict__ ca_a,
                       const float* __restrict__ ca_wh, const float* __restrict__ ca_ww)
{
    int gw = (blockIdx.x * blockDim.x + threadIdx.x) >> 5;   // one warp per (b, pos)
    int lane = threadIdx.x & 31;
    if (gw >= NB * (NH + NW)) return;
    int b = gw / (NH + NW);
    int pos = gw % (NH + NW);
    bool isH = pos < NH;
    const float* src = isH ? (g_colmean, g_rowmean + (size_t)b * NC * NH + pos)
                           : (g_colmean + (size_t)b * NC * NW + (pos - NH));
    int stride = isH ? NH : NW;

    float m0 = src[lane * stride];
    float m1 = src[(lane + 32) * stride];
    float m2 = src[(lane + 64) * stride];

    float y[8];
    #pragma unroll
    for (int mip = 0; mip < 8; mip++) {
        float z = ca_w1[mip * NC + lane] * m0
                + ca_w1[mip * NC + lane + 32] * m1
                + ca_w1[mip * NC + lane + 64] * m2;
        #pragma unroll
        for (int s2 = 16; s2 > 0; s2 >>= 1)
            z += __shfl_xor_sync(0xffffffffu, z, s2);
        float sc = ca_g[mip] * rsqrtf(ca_v[mip] + EPSV);
        z = (z - ca_m[mip]) * sc + ca_b[mip];
        y[mip] = (z >= 0.f) ? z : ca_a[mip] * z;
    }

    const float* wmat = isH ? ca_wh : ca_ww;
    float* dst = isH ? (g_ah + (size_t)b * NC * NH + pos)
                     : (g_aw + (size_t)b * NC * NW + (pos - NH));
    #pragma unroll
    for (int k = 0; k < 3; k++) {
        int c = lane + k * 32;
        float z = 0.f;
        #pragma unroll
        for (int mip = 0; mip < 8; mip++)
            z += wmat[c * 8 + mip] * y[mip];
        dst[c * stride] = 1.0f / (1.0f + expf(-z));
    }
}

__global__ void k_final(float* __restrict__ out)
{
    int i = blockIdx.x * blockDim.x + threadIdx.x;   // one float4 each
    if (i >= NB * NC * NH * NW / 4) return;
    int w4 = i & (NW / 4 - 1);
    int h  = (i >> 5) & (NH - 1);
    int bc = i >> 12;
    float ah = g_ah[bc * NH + h];
    float4 aw = *(const float4*)(g_aw + bc * NW + w4 * 4);
    float4 v  = *(const float4*)(g_out + (((size_t)bc * NH + h) * NW) + w4 * 4);
    float4 r;
    r.x = v.x * ah * aw.x;
    r.y = v.y * ah * aw.y;
    r.z = v.z * ah * aw.z;
    r.w = v.w * ah * aw.w;
    ((float4*)out)[i] = r;
}

extern "C" void kernel_launch(void* const* d_in, const int* in_sizes, int n_in,
                              void* d_out, int out_size)
{
    const float* x      = (const float*)d_in[0];
    const float* r_m    = (const float*)d_in[1];
    const float* wh_m   = (const float*)d_in[2];
    const float* ww_m   = (const float*)d_in[3];
    const float* r_l    = (const float*)d_in[4];
    const float* wh_l   = (const float*)d_in[5];
    const float* ww_l   = (const float*)d_in[6];
    const float* w_fuse = (const float*)d_in[7];
    const float* bnf_g  = (const float*)d_in[8];
    const float* bnf_b  = (const float*)d_in[9];
    const float* bnf_m  = (const float*)d_in[10];
    const float* bnf_v  = (const float*)d_in[11];
    const float* dg_wh  = (const float*)d_in[12];
    const float* dg_ww  = (const float*)d_in[13];
    const float* dg_g   = (const float*)d_in[14];
    const float* dg_b   = (const float*)d_in[15];
    const float* dg_m   = (const float*)d_in[16];
    const float* dg_v   = (const float*)d_in[17];
    const float* act_a  = (const float*)d_in[18];
    const float* ca_w1  = (const float*)d_in[19];
    const float* ca_g   = (const float*)d_in[20];
    const float* ca_b   = (const float*)d_in[21];
    const float* ca_m   = (const float*)d_in[22];
    const float* ca_v   = (const float*)d_in[23];
    const float* ca_a   = (const float*)d_in[24];
    const float* ca_wh  = (const float*)d_in[25];
    const float* ca_ww  = (const float*)d_in[26];

    const int smem_bytes = SM_FLOATS * (int)sizeof(float);
    cudaFuncSetAttribute(k_main, cudaFuncAttributeMaxDynamicSharedMemorySize, smem_bytes);

    dim3 g1(NH, NB);
    k_main<<<g1, 256, smem_bytes>>>(x, r_m, wh_m, ww_m, r_l, wh_l, ww_l, w_fuse,
                                    bnf_g, bnf_b, bnf_m, bnf_v,
                                    dg_wh, dg_ww, dg_g, dg_b, dg_m, dg_v, act_a);

    k_colmean<<<(NB * NC * NW + 255) / 256, 256>>>();

    k_attn<<<(NB * (NH + NW) * 32 + 255) / 256, 256>>>(ca_w1, ca_g, ca_b, ca_m,
                                                       ca_v, ca_a, ca_wh, ca_ww);

    k_final<<<(NB * NC * NH * NW / 4 + 255) / 256, 256>>>((float*)d_out);
}